// round 2
// baseline (speedup 1.0000x reference)
#include <cuda_runtime.h>
#include <cuda_bf16.h>
#include <math.h>

// Problem constants (fixed shapes for this problem instance)
#define MAXN 50000
#define DIM  128
#define NGRAPH 64

// Scratch buffers (no cudaMalloc allowed) — 3 x 25.6 MB
__device__ __align__(16) float g_agg[MAXN * DIM];
__device__ __align__(16) float g_t  [MAXN * DIM];
__device__ __align__(16) float g_h  [MAXN * DIM];

// ---------------------------------------------------------------------------
// copy: dst = src (float4 vectorized), n4 = number of float4 elements
// ---------------------------------------------------------------------------
__global__ void copy_f4(const float4* __restrict__ src, float4* __restrict__ dst, int n4) {
    int i = blockIdx.x * blockDim.x + threadIdx.x;
    if (i < n4) dst[i] = src[i];
}

// ---------------------------------------------------------------------------
// scatter_add: agg[dst] += x[src] for each edge. One warp per edge,
// each lane handles 4 consecutive features (float4 read, 4 scalar atomics).
// Indices are int32 (JAX x64-disabled downcasts int64 -> int32).
// ---------------------------------------------------------------------------
__global__ void scatter_add(const float4* __restrict__ x,
                            const int* __restrict__ ei,
                            float* __restrict__ agg, int E) {
    long long gid = (long long)blockIdx.x * blockDim.x + threadIdx.x;
    int e    = (int)(gid >> 5);
    int lane = (int)(gid & 31);
    if (e >= E) return;
    int src = __ldg(&ei[e]);
    int dst = __ldg(&ei[E + e]);
    float4 v = x[src * 32 + lane];
    float* p = agg + (long long)dst * DIM + lane * 4;
    atomicAdd(p + 0, v.x);
    atomicAdd(p + 1, v.y);
    atomicAdd(p + 2, v.z);
    atomicAdd(p + 3, v.w);
}

// ---------------------------------------------------------------------------
// gemm_bias_relu: C[N,128] = relu(A[N,128] @ W[128,128] + bias)
// BM=64 rows per block, 256 threads, 4x8 micro-tile per thread, K chunked by 32.
// ---------------------------------------------------------------------------
__global__ void __launch_bounds__(256) gemm_bias_relu(
    const float* __restrict__ A, const float* __restrict__ W,
    const float* __restrict__ bias, float* __restrict__ C, int N)
{
    __shared__ float Ws[32][128];   // W chunk: 32 k-rows x 128 cols
    __shared__ float As[64][36];    // A chunk: 64 rows x 32 k (pad to 36)

    const int tid  = threadIdx.x;
    const int row0 = blockIdx.x * 64;
    const int tx   = tid & 15;   // col group: 8 cols each
    const int ty   = tid >> 4;   // row group: 4 rows each

    float acc[4][8];
    #pragma unroll
    for (int i = 0; i < 4; i++)
        #pragma unroll
        for (int j = 0; j < 8; j++) acc[i][j] = 0.f;

    for (int kb = 0; kb < 4; kb++) {
        // Load W chunk: 1024 float4, 4 per thread
        #pragma unroll
        for (int i = 0; i < 4; i++) {
            int idx = tid + i * 256;         // 0..1023
            int r = idx >> 5;                // 0..31
            int c = idx & 31;                // float4 col
            float4 v = ((const float4*)W)[(kb * 32 + r) * 32 + c];
            *(float4*)&Ws[r][c * 4] = v;
        }
        // Load A chunk: 512 float4, 2 per thread
        #pragma unroll
        for (int i = 0; i < 2; i++) {
            int idx = tid + i * 256;         // 0..511
            int r = idx >> 3;                // 0..63
            int c = idx & 7;                 // float4 col within chunk
            int g = row0 + r;
            float4 v = make_float4(0.f, 0.f, 0.f, 0.f);
            if (g < N) v = ((const float4*)A)[g * 32 + kb * 8 + c];
            *(float4*)&As[r][c * 4] = v;
        }
        __syncthreads();

        #pragma unroll
        for (int k = 0; k < 32; k++) {
            float a[4];
            #pragma unroll
            for (int i = 0; i < 4; i++) a[i] = As[ty * 4 + i][k];
            float4 b0 = *(const float4*)&Ws[k][tx * 8];
            float4 b1 = *(const float4*)&Ws[k][tx * 8 + 4];
            float b[8] = {b0.x, b0.y, b0.z, b0.w, b1.x, b1.y, b1.z, b1.w};
            #pragma unroll
            for (int i = 0; i < 4; i++)
                #pragma unroll
                for (int j = 0; j < 8; j++)
                    acc[i][j] = fmaf(a[i], b[j], acc[i][j]);
        }
        __syncthreads();
    }

    float bb[8];
    #pragma unroll
    for (int j = 0; j < 8; j++) bb[j] = bias[tx * 8 + j];

    #pragma unroll
    for (int i = 0; i < 4; i++) {
        int g = row0 + ty * 4 + i;
        if (g < N) {
            float4 o0, o1;
            o0.x = fmaxf(acc[i][0] + bb[0], 0.f);
            o0.y = fmaxf(acc[i][1] + bb[1], 0.f);
            o0.z = fmaxf(acc[i][2] + bb[2], 0.f);
            o0.w = fmaxf(acc[i][3] + bb[3], 0.f);
            o1.x = fmaxf(acc[i][4] + bb[4], 0.f);
            o1.y = fmaxf(acc[i][5] + bb[5], 0.f);
            o1.z = fmaxf(acc[i][6] + bb[6], 0.f);
            o1.w = fmaxf(acc[i][7] + bb[7], 0.f);
            *(float4*)&C[(long long)g * DIM + tx * 8]     = o0;
            *(float4*)&C[(long long)g * DIM + tx * 8 + 4] = o1;
        }
    }
}

// ---------------------------------------------------------------------------
// pool_ffn: per-graph mean pool (batch sorted -> binary search range),
// then relu(pooled@wf1+bf1)@wf2+bf2, softmax. One block of 256 per graph.
// ---------------------------------------------------------------------------
__global__ void __launch_bounds__(256) pool_ffn(
    const float* __restrict__ h, const int* __restrict__ batch, int N,
    const float* __restrict__ wf1, const float* __restrict__ bf1,
    const float* __restrict__ wf2, const float* __restrict__ bf2,
    float* __restrict__ out)
{
    const int g    = blockIdx.x;
    const int tid  = threadIdx.x;
    const int f    = tid & 127;
    const int half = tid >> 7;

    // lower_bound(batch, g) and lower_bound(batch, g+1)
    int start, end;
    {
        int v = g;
        int lo = 0, hi = N;
        while (lo < hi) { int m = (lo + hi) >> 1; if (batch[m] < v) lo = m + 1; else hi = m; }
        start = lo;
        v = g + 1; lo = start; hi = N;
        while (lo < hi) { int m = (lo + hi) >> 1; if (batch[m] < v) lo = m + 1; else hi = m; }
        end = lo;
    }

    float a0 = 0.f, a1 = 0.f, a2 = 0.f, a3 = 0.f;
    int n = start + half;
    for (; n + 6 < end; n += 8) {
        a0 += h[(long long)(n    ) * DIM + f];
        a1 += h[(long long)(n + 2) * DIM + f];
        a2 += h[(long long)(n + 4) * DIM + f];
        a3 += h[(long long)(n + 6) * DIM + f];
    }
    for (; n < end; n += 2) a0 += h[(long long)n * DIM + f];
    float s = (a0 + a1) + (a2 + a3);

    __shared__ float ps[2][128];
    __shared__ float pooled_s[128];
    __shared__ float h1[128];
    __shared__ float o[10];

    ps[half][f] = s;
    __syncthreads();

    float cnt = fmaxf((float)(end - start), 1.0f);
    if (tid < 128) pooled_s[tid] = (ps[0][tid] + ps[1][tid]) / cnt;
    __syncthreads();

    if (tid < 128) {
        float acc = bf1[tid];
        #pragma unroll 8
        for (int k = 0; k < 128; k++) acc = fmaf(pooled_s[k], wf1[k * 128 + tid], acc);
        h1[tid] = fmaxf(acc, 0.f);
    }
    __syncthreads();

    if (tid < 10) {
        float acc = bf2[tid];
        #pragma unroll 8
        for (int k = 0; k < 128; k++) acc = fmaf(h1[k], wf2[k * 10 + tid], acc);
        o[tid] = acc;
    }
    __syncthreads();

    if (tid == 0) {
        float m = o[0];
        #pragma unroll
        for (int c = 1; c < 10; c++) m = fmaxf(m, o[c]);
        float e[10]; float sum = 0.f;
        #pragma unroll
        for (int c = 0; c < 10; c++) { e[c] = __expf(o[c] - m); sum += e[c]; }
        float inv = 1.f / sum;
        #pragma unroll
        for (int c = 0; c < 10; c++) out[g * 10 + c] = e[c] * inv;
    }
}

// ---------------------------------------------------------------------------
extern "C" void kernel_launch(void* const* d_in, const int* in_sizes, int n_in,
                              void* d_out, int out_size) {
    const float* x     = (const float*)d_in[0];
    const int*   ei    = (const int*)d_in[1];     // int32 (JAX x64 disabled)
    const int*   batch = (const int*)d_in[2];     // int32
    const float* w[6] = { (const float*)d_in[3],  (const float*)d_in[5],
                          (const float*)d_in[7],  (const float*)d_in[9],
                          (const float*)d_in[11], (const float*)d_in[13] };
    const float* b[6] = { (const float*)d_in[4],  (const float*)d_in[6],
                          (const float*)d_in[8],  (const float*)d_in[10],
                          (const float*)d_in[12], (const float*)d_in[14] };
    const float* wf1 = (const float*)d_in[15];
    const float* bf1 = (const float*)d_in[16];
    const float* wf2 = (const float*)d_in[17];
    const float* bf2 = (const float*)d_in[18];

    const int N = in_sizes[0] / DIM;
    const int E = in_sizes[1] / 2;

    float *agg, *t, *hbuf;
    cudaGetSymbolAddress((void**)&agg,  g_agg);
    cudaGetSymbolAddress((void**)&t,    g_t);
    cudaGetSymbolAddress((void**)&hbuf, g_h);

    const int n4 = N * 32;                       // float4 count per matrix
    const int copy_blocks = (n4 + 255) / 256;
    const long long scat_threads = (long long)E * 32;
    const int scat_blocks = (int)((scat_threads + 255) / 256);
    const int gemm_blocks = (N + 63) / 64;

    for (int L = 0; L < 3; L++) {
        const float* in = (L == 0) ? x : hbuf;
        copy_f4<<<copy_blocks, 256>>>((const float4*)in, (float4*)agg, n4);
        scatter_add<<<scat_blocks, 256>>>((const float4*)in, ei, agg, E);
        gemm_bias_relu<<<gemm_blocks, 256>>>(agg, w[2 * L],     b[2 * L],     t,    N);
        gemm_bias_relu<<<gemm_blocks, 256>>>(t,   w[2 * L + 1], b[2 * L + 1], hbuf, N);
    }
    pool_ffn<<<NGRAPH, 256>>>(hbuf, batch, N, wf1, bf1, wf2, bf2, (float*)d_out);
}

// round 3
// speedup vs baseline: 1.7890x; 1.7890x over previous
#include <cuda_runtime.h>
#include <cuda_bf16.h>
#include <math.h>

#define MAXN 50000
#define DIM  128
#define NGRAPH 64

// Scratch buffers (no cudaMalloc allowed)
__device__ __align__(16) float g_agg[MAXN * DIM];
__device__ __align__(16) float g_t  [MAXN * DIM];
__device__ __align__(16) float g_h  [MAXN * DIM];

// ---------------------------------------------------------------------------
// zero_f4: dst = 0 (write-only)
// ---------------------------------------------------------------------------
__global__ void zero_f4(float4* __restrict__ dst, int n4) {
    int i = blockIdx.x * blockDim.x + threadIdx.x;
    if (i < n4) dst[i] = make_float4(0.f, 0.f, 0.f, 0.f);
}

// ---------------------------------------------------------------------------
// scatter_add: agg[dst] += x[src]. One warp per edge, one red.global.v4.f32
// per lane (4 floats). Indices int32.
// ---------------------------------------------------------------------------
__global__ void scatter_add(const float4* __restrict__ x,
                            const int* __restrict__ ei,
                            float* __restrict__ agg, int E) {
    long long gid = (long long)blockIdx.x * blockDim.x + threadIdx.x;
    int e    = (int)(gid >> 5);
    int lane = (int)(gid & 31);
    if (e >= E) return;
    int src = __ldg(&ei[e]);
    int dst = __ldg(&ei[E + e]);
    float4 v = x[src * 32 + lane];
    float* p = agg + (long long)dst * DIM + lane * 4;
    asm volatile("red.global.add.v4.f32 [%0], {%1, %2, %3, %4};"
                 :: "l"(p), "f"(v.x), "f"(v.y), "f"(v.z), "f"(v.w)
                 : "memory");
}

// ---------------------------------------------------------------------------
// gemm_bias_relu: C[N,128] = relu((A [+ A2]) @ W[128,128] + bias)
// BM=128 rows/block, 256 threads, 8x8 micro-tile, K chunked by 32.
// A chunk stored k-major (transposed) so inner loop is 4x LDS.128 per k.
// ---------------------------------------------------------------------------
__global__ void __launch_bounds__(256) gemm_bias_relu(
    const float* __restrict__ A, const float* __restrict__ A2,
    const float* __restrict__ W, const float* __restrict__ bias,
    float* __restrict__ C, int N)
{
    __shared__ float Ws[32][128];    // W chunk: 32 k-rows x 128 cols
    __shared__ float As[32][132];    // A chunk transposed: As[k][row], pad 132 (16B-aligned rows)

    const int tid  = threadIdx.x;
    const int row0 = blockIdx.x * 128;
    const int tx   = tid & 15;    // 8 cols each  -> cols tx*8..tx*8+7
    const int ty   = tid >> 4;    // 8 rows each  -> rows ty*8..ty*8+7

    float acc[8][8];
    #pragma unroll
    for (int i = 0; i < 8; i++)
        #pragma unroll
        for (int j = 0; j < 8; j++) acc[i][j] = 0.f;

    for (int kb = 0; kb < 4; kb++) {
        // Load W chunk: 32 rows x 32 float4 = 1024 f4, 4 per thread
        #pragma unroll
        for (int i = 0; i < 4; i++) {
            int idx = tid + i * 256;          // 0..1023
            int r = idx >> 5;                 // 0..31 (k row)
            int c = idx & 31;                 // f4 col
            float4 v = ((const float4*)W)[(kb * 32 + r) * 32 + c];
            *(float4*)&Ws[r][c * 4] = v;
        }
        // Load A chunk: 128 rows x 8 f4 = 1024 f4, 4 per thread, store transposed
        #pragma unroll
        for (int i = 0; i < 4; i++) {
            int idx = tid + i * 256;          // 0..1023
            int r  = idx >> 3;                // 0..127 (row within tile)
            int c4 = idx & 7;                 // f4 index within k-chunk
            int g = row0 + r;
            float4 v = make_float4(0.f, 0.f, 0.f, 0.f);
            if (g < N) {
                v = ((const float4*)A)[g * 32 + kb * 8 + c4];
                if (A2) {
                    float4 u = ((const float4*)A2)[g * 32 + kb * 8 + c4];
                    v.x += u.x; v.y += u.y; v.z += u.z; v.w += u.w;
                }
            }
            int k0 = c4 * 4;
            As[k0 + 0][r] = v.x;
            As[k0 + 1][r] = v.y;
            As[k0 + 2][r] = v.z;
            As[k0 + 3][r] = v.w;
        }
        __syncthreads();

        #pragma unroll
        for (int k = 0; k < 32; k++) {
            float4 a0 = *(const float4*)&As[k][ty * 8];
            float4 a1 = *(const float4*)&As[k][ty * 8 + 4];
            float4 b0 = *(const float4*)&Ws[k][tx * 8];
            float4 b1 = *(const float4*)&Ws[k][tx * 8 + 4];
            float a[8] = {a0.x, a0.y, a0.z, a0.w, a1.x, a1.y, a1.z, a1.w};
            float b[8] = {b0.x, b0.y, b0.z, b0.w, b1.x, b1.y, b1.z, b1.w};
            #pragma unroll
            for (int i = 0; i < 8; i++)
                #pragma unroll
                for (int j = 0; j < 8; j++)
                    acc[i][j] = fmaf(a[i], b[j], acc[i][j]);
        }
        __syncthreads();
    }

    float bb[8];
    #pragma unroll
    for (int j = 0; j < 8; j++) bb[j] = bias[tx * 8 + j];

    #pragma unroll
    for (int i = 0; i < 8; i++) {
        int g = row0 + ty * 8 + i;
        if (g < N) {
            float4 o0, o1;
            o0.x = fmaxf(acc[i][0] + bb[0], 0.f);
            o0.y = fmaxf(acc[i][1] + bb[1], 0.f);
            o0.z = fmaxf(acc[i][2] + bb[2], 0.f);
            o0.w = fmaxf(acc[i][3] + bb[3], 0.f);
            o1.x = fmaxf(acc[i][4] + bb[4], 0.f);
            o1.y = fmaxf(acc[i][5] + bb[5], 0.f);
            o1.z = fmaxf(acc[i][6] + bb[6], 0.f);
            o1.w = fmaxf(acc[i][7] + bb[7], 0.f);
            *(float4*)&C[(long long)g * DIM + tx * 8]     = o0;
            *(float4*)&C[(long long)g * DIM + tx * 8 + 4] = o1;
        }
    }
}

// ---------------------------------------------------------------------------
// pool_ffn: per-graph mean pool (batch sorted -> binary search), FFN, softmax
// ---------------------------------------------------------------------------
__global__ void __launch_bounds__(256) pool_ffn(
    const float* __restrict__ h, const int* __restrict__ batch, int N,
    const float* __restrict__ wf1, const float* __restrict__ bf1,
    const float* __restrict__ wf2, const float* __restrict__ bf2,
    float* __restrict__ out)
{
    const int g    = blockIdx.x;
    const int tid  = threadIdx.x;
    const int f    = tid & 127;
    const int half = tid >> 7;

    int start, end;
    {
        int v = g;
        int lo = 0, hi = N;
        while (lo < hi) { int m = (lo + hi) >> 1; if (batch[m] < v) lo = m + 1; else hi = m; }
        start = lo;
        v = g + 1; lo = start; hi = N;
        while (lo < hi) { int m = (lo + hi) >> 1; if (batch[m] < v) lo = m + 1; else hi = m; }
        end = lo;
    }

    float a0 = 0.f, a1 = 0.f, a2 = 0.f, a3 = 0.f;
    int n = start + half;
    for (; n + 6 < end; n += 8) {
        a0 += h[(long long)(n    ) * DIM + f];
        a1 += h[(long long)(n + 2) * DIM + f];
        a2 += h[(long long)(n + 4) * DIM + f];
        a3 += h[(long long)(n + 6) * DIM + f];
    }
    for (; n < end; n += 2) a0 += h[(long long)n * DIM + f];
    float s = (a0 + a1) + (a2 + a3);

    __shared__ float ps[2][128];
    __shared__ float pooled_s[128];
    __shared__ float h1[128];
    __shared__ float o[10];

    ps[half][f] = s;
    __syncthreads();

    float cnt = fmaxf((float)(end - start), 1.0f);
    if (tid < 128) pooled_s[tid] = (ps[0][tid] + ps[1][tid]) / cnt;
    __syncthreads();

    if (tid < 128) {
        float acc = bf1[tid];
        #pragma unroll 8
        for (int k = 0; k < 128; k++) acc = fmaf(pooled_s[k], wf1[k * 128 + tid], acc);
        h1[tid] = fmaxf(acc, 0.f);
    }
    __syncthreads();

    if (tid < 10) {
        float acc = bf2[tid];
        #pragma unroll 8
        for (int k = 0; k < 128; k++) acc = fmaf(h1[k], wf2[k * 10 + tid], acc);
        o[tid] = acc;
    }
    __syncthreads();

    if (tid == 0) {
        float m = o[0];
        #pragma unroll
        for (int c = 1; c < 10; c++) m = fmaxf(m, o[c]);
        float e[10]; float sum = 0.f;
        #pragma unroll
        for (int c = 0; c < 10; c++) { e[c] = __expf(o[c] - m); sum += e[c]; }
        float inv = 1.f / sum;
        #pragma unroll
        for (int c = 0; c < 10; c++) out[g * 10 + c] = e[c] * inv;
    }
}

// ---------------------------------------------------------------------------
extern "C" void kernel_launch(void* const* d_in, const int* in_sizes, int n_in,
                              void* d_out, int out_size) {
    const float* x     = (const float*)d_in[0];
    const int*   ei    = (const int*)d_in[1];
    const int*   batch = (const int*)d_in[2];
    const float* w[6] = { (const float*)d_in[3],  (const float*)d_in[5],
                          (const float*)d_in[7],  (const float*)d_in[9],
                          (const float*)d_in[11], (const float*)d_in[13] };
    const float* b[6] = { (const float*)d_in[4],  (const float*)d_in[6],
                          (const float*)d_in[8],  (const float*)d_in[10],
                          (const float*)d_in[12], (const float*)d_in[14] };
    const float* wf1 = (const float*)d_in[15];
    const float* bf1 = (const float*)d_in[16];
    const float* wf2 = (const float*)d_in[17];
    const float* bf2 = (const float*)d_in[18];

    const int N = in_sizes[0] / DIM;
    const int E = in_sizes[1] / 2;

    float *agg, *t, *hbuf;
    cudaGetSymbolAddress((void**)&agg,  g_agg);
    cudaGetSymbolAddress((void**)&t,    g_t);
    cudaGetSymbolAddress((void**)&hbuf, g_h);

    const int n4 = N * 32;
    const int zero_blocks = (n4 + 255) / 256;
    const long long scat_threads = (long long)E * 32;
    const int scat_blocks = (int)((scat_threads + 255) / 256);
    const int gemm_blocks = (N + 127) / 128;

    for (int L = 0; L < 3; L++) {
        const float* in = (L == 0) ? x : hbuf;
        zero_f4<<<zero_blocks, 256>>>((float4*)agg, n4);
        scatter_add<<<scat_blocks, 256>>>((const float4*)in, ei, agg, E);
        // GEMM1: A = agg + in (self term fused), GEMM2: plain
        gemm_bias_relu<<<gemm_blocks, 256>>>(agg, in,      w[2 * L],     b[2 * L],     t,    N);
        gemm_bias_relu<<<gemm_blocks, 256>>>(t,   nullptr, w[2 * L + 1], b[2 * L + 1], hbuf, N);
    }
    pool_ffn<<<NGRAPH, 256>>>(hbuf, batch, N, wf1, bf1, wf2, bf2, (float*)d_out);
}

// round 4
// speedup vs baseline: 2.0442x; 1.1426x over previous
#include <cuda_runtime.h>
#include <cuda_bf16.h>
#include <math.h>
#include <stdint.h>

#define MAXN 50000
#define DIM  128
#define NGRAPH 64

// Scratch buffers (no cudaMalloc allowed)
__device__ __align__(16) float g_agg[MAXN * DIM];
__device__ __align__(16) float g_t  [MAXN * DIM];
__device__ __align__(16) float g_h  [MAXN * DIM];

// ---------------------------------------------------------------------------
__global__ void zero_f4(float4* __restrict__ dst, int n4) {
    int i = blockIdx.x * blockDim.x + threadIdx.x;
    if (i < n4) dst[i] = make_float4(0.f, 0.f, 0.f, 0.f);
}

// ---------------------------------------------------------------------------
// scatter_add: agg[dst] += x[src]. One warp per edge, one red.global.v4.f32
// per lane. Indices int32.
// ---------------------------------------------------------------------------
__global__ void scatter_add(const float4* __restrict__ x,
                            const int* __restrict__ ei,
                            float* __restrict__ agg, int E) {
    long long gid = (long long)blockIdx.x * blockDim.x + threadIdx.x;
    int e    = (int)(gid >> 5);
    int lane = (int)(gid & 31);
    if (e >= E) return;
    int src = __ldg(&ei[e]);
    int dst = __ldg(&ei[E + e]);
    float4 v = x[src * 32 + lane];
    float* p = agg + (long long)dst * DIM + lane * 4;
    asm volatile("red.global.add.v4.f32 [%0], {%1, %2, %3, %4};"
                 :: "l"(p), "f"(v.x), "f"(v.y), "f"(v.z), "f"(v.w)
                 : "memory");
}

// ---------------------------------------------------------------------------
// 3xTF32 tensor-core GEMM: C[N,128] = relu((A [+ A2]) @ W[128,128] + bias)
// Block: 128 rows x 128 cols, 256 threads = 8 warps (2 warpM x 4 warpN).
// Warp tile 64x32 = 4x4 fragments of m16n8k8.
// D = Ahi*Bhi + Ahi*Blo + Alo*Bhi  (near-fp32 accuracy)
// ---------------------------------------------------------------------------
__device__ __forceinline__ uint32_t f2tf32(float f) {
    uint32_t r;
    asm("cvt.rna.tf32.f32 %0, %1;" : "=r"(r) : "f"(f));
    return r;
}

__device__ __forceinline__ void mma_tf32(float d[4],
                                         const uint32_t a[4],
                                         const uint32_t b[2]) {
    asm volatile(
        "mma.sync.aligned.m16n8k8.row.col.f32.tf32.tf32.f32 "
        "{%0,%1,%2,%3}, {%4,%5,%6,%7}, {%8,%9}, {%0,%1,%2,%3};"
        : "+f"(d[0]), "+f"(d[1]), "+f"(d[2]), "+f"(d[3])
        : "r"(a[0]), "r"(a[1]), "r"(a[2]), "r"(a[3]),
          "r"(b[0]), "r"(b[1]));
}

#define AS_PITCH 36   // 128 rows x 36 (pad) — m-major
#define WS_PITCH 136  // 32 k-rows x 136 (pad) — k-major

__global__ void __launch_bounds__(256, 2) gemm_tf32(
    const float* __restrict__ A, const float* __restrict__ A2,
    const float* __restrict__ W, const float* __restrict__ bias,
    float* __restrict__ C, int N)
{
    extern __shared__ uint32_t sm[];
    uint32_t* AsHi = sm;                       // 128*36
    uint32_t* AsLo = sm + 128 * AS_PITCH;      // 128*36
    uint32_t* WsHi = sm + 2 * 128 * AS_PITCH;  // 32*136
    uint32_t* WsLo = WsHi + 32 * WS_PITCH;     // 32*136

    const int tid   = threadIdx.x;
    const int lane  = tid & 31;
    const int warp  = tid >> 5;
    const int warpM = warp >> 2;   // 0..1 -> 64 rows each
    const int warpN = warp & 3;    // 0..3 -> 32 cols each
    const int gid   = lane >> 2;   // 0..7
    const int tig   = lane & 3;    // 0..3
    const int row0  = blockIdx.x * 128;

    float acc[4][4][4];
    #pragma unroll
    for (int i = 0; i < 4; i++)
        #pragma unroll
        for (int j = 0; j < 4; j++)
            #pragma unroll
            for (int k = 0; k < 4; k++) acc[i][j][k] = 0.f;

    for (int kb = 0; kb < 4; kb++) {
        // ---- load + convert W chunk: 32 k-rows x 128 cols (1024 float4) ----
        #pragma unroll
        for (int i = 0; i < 4; i++) {
            int idx = tid + i * 256;          // 0..1023
            int r = idx >> 5;                 // k row 0..31
            int c = idx & 31;                 // float4 col
            float4 v = ((const float4*)W)[(kb * 32 + r) * 32 + c];
            float* vp = (float*)&v;
            #pragma unroll
            for (int j = 0; j < 4; j++) {
                uint32_t hi = f2tf32(vp[j]);
                float lof = vp[j] - __uint_as_float(hi);
                WsHi[r * WS_PITCH + c * 4 + j] = hi;
                WsLo[r * WS_PITCH + c * 4 + j] = f2tf32(lof);
            }
        }
        // ---- load + convert A chunk: 128 rows x 32 k (1024 float4) ----
        #pragma unroll
        for (int i = 0; i < 4; i++) {
            int idx = tid + i * 256;          // 0..1023
            int r  = idx >> 3;                // row 0..127
            int c4 = idx & 7;                 // f4 idx within k-chunk
            int g = row0 + r;
            float4 v = make_float4(0.f, 0.f, 0.f, 0.f);
            if (g < N) {
                v = ((const float4*)A)[g * 32 + kb * 8 + c4];
                if (A2) {
                    float4 u = ((const float4*)A2)[g * 32 + kb * 8 + c4];
                    v.x += u.x; v.y += u.y; v.z += u.z; v.w += u.w;
                }
            }
            float* vp = (float*)&v;
            uint4 hi4, lo4;
            uint32_t* hp = (uint32_t*)&hi4;
            uint32_t* lp = (uint32_t*)&lo4;
            #pragma unroll
            for (int j = 0; j < 4; j++) {
                uint32_t hi = f2tf32(vp[j]);
                hp[j] = hi;
                lp[j] = f2tf32(vp[j] - __uint_as_float(hi));
            }
            *(uint4*)&AsHi[r * AS_PITCH + c4 * 4] = hi4;
            *(uint4*)&AsLo[r * AS_PITCH + c4 * 4] = lo4;
        }
        __syncthreads();

        // ---- compute: 4 k-steps of 8 ----
        #pragma unroll
        for (int ks = 0; ks < 4; ks++) {
            int k0 = ks * 8;
            uint32_t bH[4][2], bL[4][2];
            #pragma unroll
            for (int nt = 0; nt < 4; nt++) {
                int cb = warpN * 32 + nt * 8 + gid;
                bH[nt][0] = WsHi[(k0 + tig) * WS_PITCH + cb];
                bH[nt][1] = WsHi[(k0 + tig + 4) * WS_PITCH + cb];
                bL[nt][0] = WsLo[(k0 + tig) * WS_PITCH + cb];
                bL[nt][1] = WsLo[(k0 + tig + 4) * WS_PITCH + cb];
            }
            #pragma unroll
            for (int mt = 0; mt < 4; mt++) {
                int rb = warpM * 64 + mt * 16;
                uint32_t aH[4], aL[4];
                aH[0] = AsHi[(rb + gid) * AS_PITCH + k0 + tig];
                aH[1] = AsHi[(rb + gid + 8) * AS_PITCH + k0 + tig];
                aH[2] = AsHi[(rb + gid) * AS_PITCH + k0 + tig + 4];
                aH[3] = AsHi[(rb + gid + 8) * AS_PITCH + k0 + tig + 4];
                aL[0] = AsLo[(rb + gid) * AS_PITCH + k0 + tig];
                aL[1] = AsLo[(rb + gid + 8) * AS_PITCH + k0 + tig];
                aL[2] = AsLo[(rb + gid) * AS_PITCH + k0 + tig + 4];
                aL[3] = AsLo[(rb + gid + 8) * AS_PITCH + k0 + tig + 4];
                #pragma unroll
                for (int nt = 0; nt < 4; nt++) {
                    mma_tf32(acc[mt][nt], aH, bH[nt]);  // hi*hi
                    mma_tf32(acc[mt][nt], aL, bH[nt]);  // lo*hi
                    mma_tf32(acc[mt][nt], aH, bL[nt]);  // hi*lo
                }
            }
        }
        __syncthreads();
    }

    // ---- epilogue: bias + relu + store ----
    #pragma unroll
    for (int nt = 0; nt < 4; nt++) {
        int cb = warpN * 32 + nt * 8;
        float2 bv = *(const float2*)&bias[cb + tig * 2];
        #pragma unroll
        for (int mt = 0; mt < 4; mt++) {
            int r0 = row0 + warpM * 64 + mt * 16 + gid;
            int r1 = r0 + 8;
            if (r0 < N) {
                float2 o;
                o.x = fmaxf(acc[mt][nt][0] + bv.x, 0.f);
                o.y = fmaxf(acc[mt][nt][1] + bv.y, 0.f);
                *(float2*)&C[(long long)r0 * DIM + cb + tig * 2] = o;
            }
            if (r1 < N) {
                float2 o;
                o.x = fmaxf(acc[mt][nt][2] + bv.x, 0.f);
                o.y = fmaxf(acc[mt][nt][3] + bv.y, 0.f);
                *(float2*)&C[(long long)r1 * DIM + cb + tig * 2] = o;
            }
        }
    }
}

#define GEMM_SMEM ((2 * 128 * AS_PITCH + 2 * 32 * WS_PITCH) * 4)

// ---------------------------------------------------------------------------
// pool_ffn: per-graph mean pool (batch sorted -> binary search), FFN, softmax
// ---------------------------------------------------------------------------
__global__ void __launch_bounds__(256) pool_ffn(
    const float* __restrict__ h, const int* __restrict__ batch, int N,
    const float* __restrict__ wf1, const float* __restrict__ bf1,
    const float* __restrict__ wf2, const float* __restrict__ bf2,
    float* __restrict__ out)
{
    const int g    = blockIdx.x;
    const int tid  = threadIdx.x;
    const int f    = tid & 127;
    const int half = tid >> 7;

    int start, end;
    {
        int v = g;
        int lo = 0, hi = N;
        while (lo < hi) { int m = (lo + hi) >> 1; if (batch[m] < v) lo = m + 1; else hi = m; }
        start = lo;
        v = g + 1; lo = start; hi = N;
        while (lo < hi) { int m = (lo + hi) >> 1; if (batch[m] < v) lo = m + 1; else hi = m; }
        end = lo;
    }

    float a0 = 0.f, a1 = 0.f, a2 = 0.f, a3 = 0.f;
    int n = start + half;
    for (; n + 6 < end; n += 8) {
        a0 += h[(long long)(n    ) * DIM + f];
        a1 += h[(long long)(n + 2) * DIM + f];
        a2 += h[(long long)(n + 4) * DIM + f];
        a3 += h[(long long)(n + 6) * DIM + f];
    }
    for (; n < end; n += 2) a0 += h[(long long)n * DIM + f];
    float s = (a0 + a1) + (a2 + a3);

    __shared__ float ps[2][128];
    __shared__ float pooled_s[128];
    __shared__ float h1[128];
    __shared__ float o[10];

    ps[half][f] = s;
    __syncthreads();

    float cnt = fmaxf((float)(end - start), 1.0f);
    if (tid < 128) pooled_s[tid] = (ps[0][tid] + ps[1][tid]) / cnt;
    __syncthreads();

    if (tid < 128) {
        float acc = bf1[tid];
        #pragma unroll 8
        for (int k = 0; k < 128; k++) acc = fmaf(pooled_s[k], wf1[k * 128 + tid], acc);
        h1[tid] = fmaxf(acc, 0.f);
    }
    __syncthreads();

    if (tid < 10) {
        float acc = bf2[tid];
        #pragma unroll 8
        for (int k = 0; k < 128; k++) acc = fmaf(h1[k], wf2[k * 10 + tid], acc);
        o[tid] = acc;
    }
    __syncthreads();

    if (tid == 0) {
        float m = o[0];
        #pragma unroll
        for (int c = 1; c < 10; c++) m = fmaxf(m, o[c]);
        float e[10]; float sum = 0.f;
        #pragma unroll
        for (int c = 0; c < 10; c++) { e[c] = __expf(o[c] - m); sum += e[c]; }
        float inv = 1.f / sum;
        #pragma unroll
        for (int c = 0; c < 10; c++) out[g * 10 + c] = e[c] * inv;
    }
}

// ---------------------------------------------------------------------------
extern "C" void kernel_launch(void* const* d_in, const int* in_sizes, int n_in,
                              void* d_out, int out_size) {
    const float* x     = (const float*)d_in[0];
    const int*   ei    = (const int*)d_in[1];
    const int*   batch = (const int*)d_in[2];
    const float* w[6] = { (const float*)d_in[3],  (const float*)d_in[5],
                          (const float*)d_in[7],  (const float*)d_in[9],
                          (const float*)d_in[11], (const float*)d_in[13] };
    const float* b[6] = { (const float*)d_in[4],  (const float*)d_in[6],
                          (const float*)d_in[8],  (const float*)d_in[10],
                          (const float*)d_in[12], (const float*)d_in[14] };
    const float* wf1 = (const float*)d_in[15];
    const float* bf1 = (const float*)d_in[16];
    const float* wf2 = (const float*)d_in[17];
    const float* bf2 = (const float*)d_in[18];

    const int N = in_sizes[0] / DIM;
    const int E = in_sizes[1] / 2;

    float *agg, *t, *hbuf;
    cudaGetSymbolAddress((void**)&agg,  g_agg);
    cudaGetSymbolAddress((void**)&t,    g_t);
    cudaGetSymbolAddress((void**)&hbuf, g_h);

    static bool attr_set = false;
    if (!attr_set) {
        cudaFuncSetAttribute(gemm_tf32,
                             cudaFuncAttributeMaxDynamicSharedMemorySize,
                             GEMM_SMEM);
        attr_set = true;
    }

    const int n4 = N * 32;
    const int zero_blocks = (n4 + 255) / 256;
    const long long scat_threads = (long long)E * 32;
    const int scat_blocks = (int)((scat_threads + 255) / 256);
    const int gemm_blocks = (N + 127) / 128;

    for (int L = 0; L < 3; L++) {
        const float* in = (L == 0) ? x : hbuf;
        zero_f4<<<zero_blocks, 256>>>((float4*)agg, n4);
        scatter_add<<<scat_blocks, 256>>>((const float4*)in, ei, agg, E);
        gemm_tf32<<<gemm_blocks, 256, GEMM_SMEM>>>(agg, in,      w[2 * L],     b[2 * L],     t,    N);
        gemm_tf32<<<gemm_blocks, 256, GEMM_SMEM>>>(t,   nullptr, w[2 * L + 1], b[2 * L + 1], hbuf, N);
    }
    pool_ffn<<<NGRAPH, 256>>>(hbuf, batch, N, wf1, bf1, wf2, bf2, (float*)d_out);
}

// round 5
// speedup vs baseline: 2.2465x; 1.0990x over previous
#include <cuda_runtime.h>
#include <cuda_bf16.h>
#include <math.h>
#include <stdint.h>

#define MAXN 50000
#define MAXE 600000
#define DIM  128
#define NGRAPH 64

// Scratch buffers (no cudaMalloc allowed)
__device__ __align__(16) float g_agg[MAXN * DIM];
__device__ __align__(16) float g_t  [MAXN * DIM];
__device__ __align__(16) float g_h  [MAXN * DIM];
__device__ int g_counts  [MAXN];
__device__ int g_rowstart[MAXN + 1];
__device__ int g_cursor  [MAXN];
__device__ int g_esorted [MAXE];

// ---------------------------------------------------------------------------
// CSR build: histogram of dst
// ---------------------------------------------------------------------------
__global__ void hist_kernel(const int* __restrict__ ei, int* __restrict__ counts, int E) {
    int e = blockIdx.x * blockDim.x + threadIdx.x;
    if (e < E) atomicAdd(&counts[ei[E + e]], 1);
}

// Single-block exclusive scan over counts -> rowstart (and cursor copy).
// 1024 threads, each handles a contiguous chunk.
__global__ void __launch_bounds__(1024) scan_kernel(
    const int* __restrict__ counts, int* __restrict__ rowstart,
    int* __restrict__ cursor, int N)
{
    __shared__ int sums[1024];
    const int tid = threadIdx.x;
    const int chunk = (N + 1023) / 1024;
    const int lo = tid * chunk;
    const int hi = min(lo + chunk, N);

    int s = 0;
    for (int i = lo; i < hi; i++) s += counts[i];
    sums[tid] = s;
    __syncthreads();

    // Hillis-Steele inclusive scan on sums
    for (int d = 1; d < 1024; d <<= 1) {
        int v = (tid >= d) ? sums[tid - d] : 0;
        __syncthreads();
        sums[tid] += v;
        __syncthreads();
    }
    int run = (tid == 0) ? 0 : sums[tid - 1];   // exclusive offset for this chunk
    for (int i = lo; i < hi; i++) {
        rowstart[i] = run;
        cursor[i]   = run;
        run += counts[i];
    }
    if (tid == 1023 && N > 0) rowstart[N] = run;
    if (N <= lo && tid == 0) rowstart[N] = sums[1023]; // safety (N>=1 always here)
}

// Fill edge lists: esorted[pos] = src, grouped by dst
__global__ void fill_kernel(const int* __restrict__ ei, int* __restrict__ cursor,
                            int* __restrict__ esorted, int E) {
    int e = blockIdx.x * blockDim.x + threadIdx.x;
    if (e < E) {
        int dst = ei[E + e];
        int pos = atomicAdd(&cursor[dst], 1);
        esorted[pos] = ei[e];
    }
}

// ---------------------------------------------------------------------------
// gather: agg[n] = x[n] + sum_{s in in-neighbors(n)} x[s]
// One warp per node; lane owns one float4 of the 128-dim row.
// ---------------------------------------------------------------------------
__global__ void __launch_bounds__(256) gather_kernel(
    const float4* __restrict__ x, const int* __restrict__ rowstart,
    const int* __restrict__ esorted, float4* __restrict__ agg, int N)
{
    int warp = (blockIdx.x * blockDim.x + threadIdx.x) >> 5;
    int lane = threadIdx.x & 31;
    if (warp >= N) return;
    int node  = warp;
    int start = __ldg(&rowstart[node]);
    int end   = __ldg(&rowstart[node + 1]);

    float4 acc = x[node * 32 + lane];           // self term
    float4 a1 = make_float4(0.f, 0.f, 0.f, 0.f);
    float4 a2 = make_float4(0.f, 0.f, 0.f, 0.f);
    float4 a3 = make_float4(0.f, 0.f, 0.f, 0.f);

    int i = start;
    for (; i + 3 < end; i += 4) {
        int s0 = __ldg(&esorted[i]);
        int s1 = __ldg(&esorted[i + 1]);
        int s2 = __ldg(&esorted[i + 2]);
        int s3 = __ldg(&esorted[i + 3]);
        float4 v0 = x[s0 * 32 + lane];
        float4 v1 = x[s1 * 32 + lane];
        float4 v2 = x[s2 * 32 + lane];
        float4 v3 = x[s3 * 32 + lane];
        acc.x += v0.x; acc.y += v0.y; acc.z += v0.z; acc.w += v0.w;
        a1.x += v1.x; a1.y += v1.y; a1.z += v1.z; a1.w += v1.w;
        a2.x += v2.x; a2.y += v2.y; a2.z += v2.z; a2.w += v2.w;
        a3.x += v3.x; a3.y += v3.y; a3.z += v3.z; a3.w += v3.w;
    }
    for (; i < end; i++) {
        int s = __ldg(&esorted[i]);
        float4 v = x[s * 32 + lane];
        acc.x += v.x; acc.y += v.y; acc.z += v.z; acc.w += v.w;
    }
    acc.x += a1.x + a2.x + a3.x;
    acc.y += a1.y + a2.y + a3.y;
    acc.z += a1.z + a2.z + a3.z;
    acc.w += a1.w + a2.w + a3.w;
    agg[node * 32 + lane] = acc;
}

// ---------------------------------------------------------------------------
// 3xTF32 tensor-core GEMM: C[N,128] = relu(A @ W[128,128] + bias)
// ---------------------------------------------------------------------------
__device__ __forceinline__ uint32_t f2tf32(float f) {
    uint32_t r;
    asm("cvt.rna.tf32.f32 %0, %1;" : "=r"(r) : "f"(f));
    return r;
}

__device__ __forceinline__ void mma_tf32(float d[4],
                                         const uint32_t a[4],
                                         const uint32_t b[2]) {
    asm volatile(
        "mma.sync.aligned.m16n8k8.row.col.f32.tf32.tf32.f32 "
        "{%0,%1,%2,%3}, {%4,%5,%6,%7}, {%8,%9}, {%0,%1,%2,%3};"
        : "+f"(d[0]), "+f"(d[1]), "+f"(d[2]), "+f"(d[3])
        : "r"(a[0]), "r"(a[1]), "r"(a[2]), "r"(a[3]),
          "r"(b[0]), "r"(b[1]));
}

#define AS_PITCH 36
#define WS_PITCH 136

__global__ void __launch_bounds__(256, 2) gemm_tf32(
    const float* __restrict__ A,
    const float* __restrict__ W, const float* __restrict__ bias,
    float* __restrict__ C, int N)
{
    extern __shared__ uint32_t sm[];
    uint32_t* AsHi = sm;
    uint32_t* AsLo = sm + 128 * AS_PITCH;
    uint32_t* WsHi = sm + 2 * 128 * AS_PITCH;
    uint32_t* WsLo = WsHi + 32 * WS_PITCH;

    const int tid   = threadIdx.x;
    const int lane  = tid & 31;
    const int warp  = tid >> 5;
    const int warpM = warp >> 2;
    const int warpN = warp & 3;
    const int gid   = lane >> 2;
    const int tig   = lane & 3;
    const int row0  = blockIdx.x * 128;

    float acc[4][4][4];
    #pragma unroll
    for (int i = 0; i < 4; i++)
        #pragma unroll
        for (int j = 0; j < 4; j++)
            #pragma unroll
            for (int k = 0; k < 4; k++) acc[i][j][k] = 0.f;

    for (int kb = 0; kb < 4; kb++) {
        #pragma unroll
        for (int i = 0; i < 4; i++) {
            int idx = tid + i * 256;
            int r = idx >> 5;
            int c = idx & 31;
            float4 v = ((const float4*)W)[(kb * 32 + r) * 32 + c];
            float* vp = (float*)&v;
            #pragma unroll
            for (int j = 0; j < 4; j++) {
                uint32_t hi = f2tf32(vp[j]);
                float lof = vp[j] - __uint_as_float(hi);
                WsHi[r * WS_PITCH + c * 4 + j] = hi;
                WsLo[r * WS_PITCH + c * 4 + j] = f2tf32(lof);
            }
        }
        #pragma unroll
        for (int i = 0; i < 4; i++) {
            int idx = tid + i * 256;
            int r  = idx >> 3;
            int c4 = idx & 7;
            int g = row0 + r;
            float4 v = make_float4(0.f, 0.f, 0.f, 0.f);
            if (g < N) v = ((const float4*)A)[g * 32 + kb * 8 + c4];
            float* vp = (float*)&v;
            uint4 hi4, lo4;
            uint32_t* hp = (uint32_t*)&hi4;
            uint32_t* lp = (uint32_t*)&lo4;
            #pragma unroll
            for (int j = 0; j < 4; j++) {
                uint32_t hi = f2tf32(vp[j]);
                hp[j] = hi;
                lp[j] = f2tf32(vp[j] - __uint_as_float(hi));
            }
            *(uint4*)&AsHi[r * AS_PITCH + c4 * 4] = hi4;
            *(uint4*)&AsLo[r * AS_PITCH + c4 * 4] = lo4;
        }
        __syncthreads();

        #pragma unroll
        for (int ks = 0; ks < 4; ks++) {
            int k0 = ks * 8;
            uint32_t bH[4][2], bL[4][2];
            #pragma unroll
            for (int nt = 0; nt < 4; nt++) {
                int cb = warpN * 32 + nt * 8 + gid;
                bH[nt][0] = WsHi[(k0 + tig) * WS_PITCH + cb];
                bH[nt][1] = WsHi[(k0 + tig + 4) * WS_PITCH + cb];
                bL[nt][0] = WsLo[(k0 + tig) * WS_PITCH + cb];
                bL[nt][1] = WsLo[(k0 + tig + 4) * WS_PITCH + cb];
            }
            #pragma unroll
            for (int mt = 0; mt < 4; mt++) {
                int rb = warpM * 64 + mt * 16;
                uint32_t aH[4], aL[4];
                aH[0] = AsHi[(rb + gid) * AS_PITCH + k0 + tig];
                aH[1] = AsHi[(rb + gid + 8) * AS_PITCH + k0 + tig];
                aH[2] = AsHi[(rb + gid) * AS_PITCH + k0 + tig + 4];
                aH[3] = AsHi[(rb + gid + 8) * AS_PITCH + k0 + tig + 4];
                aL[0] = AsLo[(rb + gid) * AS_PITCH + k0 + tig];
                aL[1] = AsLo[(rb + gid + 8) * AS_PITCH + k0 + tig];
                aL[2] = AsLo[(rb + gid) * AS_PITCH + k0 + tig + 4];
                aL[3] = AsLo[(rb + gid + 8) * AS_PITCH + k0 + tig + 4];
                #pragma unroll
                for (int nt = 0; nt < 4; nt++) {
                    mma_tf32(acc[mt][nt], aH, bH[nt]);
                    mma_tf32(acc[mt][nt], aL, bH[nt]);
                    mma_tf32(acc[mt][nt], aH, bL[nt]);
                }
            }
        }
        __syncthreads();
    }

    #pragma unroll
    for (int nt = 0; nt < 4; nt++) {
        int cb = warpN * 32 + nt * 8;
        float2 bv = *(const float2*)&bias[cb + tig * 2];
        #pragma unroll
        for (int mt = 0; mt < 4; mt++) {
            int r0 = row0 + warpM * 64 + mt * 16 + gid;
            int r1 = r0 + 8;
            if (r0 < N) {
                float2 o;
                o.x = fmaxf(acc[mt][nt][0] + bv.x, 0.f);
                o.y = fmaxf(acc[mt][nt][1] + bv.y, 0.f);
                *(float2*)&C[(long long)r0 * DIM + cb + tig * 2] = o;
            }
            if (r1 < N) {
                float2 o;
                o.x = fmaxf(acc[mt][nt][2] + bv.x, 0.f);
                o.y = fmaxf(acc[mt][nt][3] + bv.y, 0.f);
                *(float2*)&C[(long long)r1 * DIM + cb + tig * 2] = o;
            }
        }
    }
}

#define GEMM_SMEM ((2 * 128 * AS_PITCH + 2 * 32 * WS_PITCH) * 4)

// ---------------------------------------------------------------------------
// pool_ffn
// ---------------------------------------------------------------------------
__global__ void __launch_bounds__(256) pool_ffn(
    const float* __restrict__ h, const int* __restrict__ batch, int N,
    const float* __restrict__ wf1, const float* __restrict__ bf1,
    const float* __restrict__ wf2, const float* __restrict__ bf2,
    float* __restrict__ out)
{
    const int g    = blockIdx.x;
    const int tid  = threadIdx.x;
    const int f    = tid & 127;
    const int half = tid >> 7;

    int start, end;
    {
        int v = g;
        int lo = 0, hi = N;
        while (lo < hi) { int m = (lo + hi) >> 1; if (batch[m] < v) lo = m + 1; else hi = m; }
        start = lo;
        v = g + 1; lo = start; hi = N;
        while (lo < hi) { int m = (lo + hi) >> 1; if (batch[m] < v) lo = m + 1; else hi = m; }
        end = lo;
    }

    float a0 = 0.f, a1 = 0.f, a2 = 0.f, a3 = 0.f;
    int n = start + half;
    for (; n + 6 < end; n += 8) {
        a0 += h[(long long)(n    ) * DIM + f];
        a1 += h[(long long)(n + 2) * DIM + f];
        a2 += h[(long long)(n + 4) * DIM + f];
        a3 += h[(long long)(n + 6) * DIM + f];
    }
    for (; n < end; n += 2) a0 += h[(long long)n * DIM + f];
    float s = (a0 + a1) + (a2 + a3);

    __shared__ float ps[2][128];
    __shared__ float pooled_s[128];
    __shared__ float h1[128];
    __shared__ float o[10];

    ps[half][f] = s;
    __syncthreads();

    float cnt = fmaxf((float)(end - start), 1.0f);
    if (tid < 128) pooled_s[tid] = (ps[0][tid] + ps[1][tid]) / cnt;
    __syncthreads();

    if (tid < 128) {
        float acc = bf1[tid];
        #pragma unroll 8
        for (int k = 0; k < 128; k++) acc = fmaf(pooled_s[k], wf1[k * 128 + tid], acc);
        h1[tid] = fmaxf(acc, 0.f);
    }
    __syncthreads();

    if (tid < 10) {
        float acc = bf2[tid];
        #pragma unroll 8
        for (int k = 0; k < 128; k++) acc = fmaf(h1[k], wf2[k * 10 + tid], acc);
        o[tid] = acc;
    }
    __syncthreads();

    if (tid == 0) {
        float m = o[0];
        #pragma unroll
        for (int c = 1; c < 10; c++) m = fmaxf(m, o[c]);
        float e[10]; float sum = 0.f;
        #pragma unroll
        for (int c = 0; c < 10; c++) { e[c] = __expf(o[c] - m); sum += e[c]; }
        float inv = 1.f / sum;
        #pragma unroll
        for (int c = 0; c < 10; c++) out[g * 10 + c] = e[c] * inv;
    }
}

// ---------------------------------------------------------------------------
extern "C" void kernel_launch(void* const* d_in, const int* in_sizes, int n_in,
                              void* d_out, int out_size) {
    const float* x     = (const float*)d_in[0];
    const int*   ei    = (const int*)d_in[1];
    const int*   batch = (const int*)d_in[2];
    const float* w[6] = { (const float*)d_in[3],  (const float*)d_in[5],
                          (const float*)d_in[7],  (const float*)d_in[9],
                          (const float*)d_in[11], (const float*)d_in[13] };
    const float* b[6] = { (const float*)d_in[4],  (const float*)d_in[6],
                          (const float*)d_in[8],  (const float*)d_in[10],
                          (const float*)d_in[12], (const float*)d_in[14] };
    const float* wf1 = (const float*)d_in[15];
    const float* bf1 = (const float*)d_in[16];
    const float* wf2 = (const float*)d_in[17];
    const float* bf2 = (const float*)d_in[18];

    const int N = in_sizes[0] / DIM;
    const int E = in_sizes[1] / 2;

    float *agg, *t, *hbuf;
    int *counts, *rowstart, *cursor, *esorted;
    cudaGetSymbolAddress((void**)&agg,      g_agg);
    cudaGetSymbolAddress((void**)&t,        g_t);
    cudaGetSymbolAddress((void**)&hbuf,     g_h);
    cudaGetSymbolAddress((void**)&counts,   g_counts);
    cudaGetSymbolAddress((void**)&rowstart, g_rowstart);
    cudaGetSymbolAddress((void**)&cursor,   g_cursor);
    cudaGetSymbolAddress((void**)&esorted,  g_esorted);

    static bool attr_set = false;
    if (!attr_set) {
        cudaFuncSetAttribute(gemm_tf32,
                             cudaFuncAttributeMaxDynamicSharedMemorySize,
                             GEMM_SMEM);
        attr_set = true;
    }

    // ---- CSR build ----
    cudaMemsetAsync(counts, 0, N * sizeof(int));
    const int eb = (E + 255) / 256;
    hist_kernel<<<eb, 256>>>(ei, counts, E);
    scan_kernel<<<1, 1024>>>(counts, rowstart, cursor, N);
    fill_kernel<<<eb, 256>>>(ei, cursor, esorted, E);

    const int gather_blocks = (N * 32 + 255) / 256;   // warp per node, 8 warps/block
    const int gemm_blocks = (N + 127) / 128;

    for (int L = 0; L < 3; L++) {
        const float* in = (L == 0) ? x : hbuf;
        gather_kernel<<<gather_blocks, 256>>>((const float4*)in, rowstart, esorted,
                                              (float4*)agg, N);
        gemm_tf32<<<gemm_blocks, 256, GEMM_SMEM>>>(agg, w[2 * L],     b[2 * L],     t,    N);
        gemm_tf32<<<gemm_blocks, 256, GEMM_SMEM>>>(t,   w[2 * L + 1], b[2 * L + 1], hbuf, N);
    }
    pool_ffn<<<NGRAPH, 256>>>(hbuf, batch, N, wf1, bf1, wf2, bf2, (float*)d_out);
}

// round 6
// speedup vs baseline: 2.4146x; 1.0748x over previous
#include <cuda_runtime.h>
#include <cuda_bf16.h>
#include <math.h>
#include <stdint.h>

#define MAXN 50000
#define MAXE 600000
#define DIM  128
#define NGRAPH 64

// Scratch buffers (no cudaMalloc allowed)
__device__ __align__(16) float g_agg[MAXN * DIM];
__device__ __align__(16) float g_h  [MAXN * DIM];
__device__ int g_counts  [MAXN];
__device__ int g_rowstart[MAXN + 1];
__device__ int g_cursor  [MAXN];
__device__ int g_esorted [MAXE];

// ---------------------------------------------------------------------------
// CSR build
// ---------------------------------------------------------------------------
__global__ void hist_kernel(const int* __restrict__ ei, int* __restrict__ counts, int E) {
    int e = blockIdx.x * blockDim.x + threadIdx.x;
    if (e < E) atomicAdd(&counts[ei[E + e]], 1);
}

__global__ void __launch_bounds__(1024) scan_kernel(
    const int* __restrict__ counts, int* __restrict__ rowstart,
    int* __restrict__ cursor, int N)
{
    __shared__ int sums[1024];
    const int tid = threadIdx.x;
    const int chunk = (N + 1023) / 1024;
    const int lo = tid * chunk;
    const int hi = min(lo + chunk, N);

    int s = 0;
    for (int i = lo; i < hi; i++) s += counts[i];
    sums[tid] = s;
    __syncthreads();

    for (int d = 1; d < 1024; d <<= 1) {
        int v = (tid >= d) ? sums[tid - d] : 0;
        __syncthreads();
        sums[tid] += v;
        __syncthreads();
    }
    int run = (tid == 0) ? 0 : sums[tid - 1];
    for (int i = lo; i < hi; i++) {
        rowstart[i] = run;
        cursor[i]   = run;
        run += counts[i];
    }
    if (tid == 1023 && N > 0) rowstart[N] = run;
}

__global__ void fill_kernel(const int* __restrict__ ei, int* __restrict__ cursor,
                            int* __restrict__ esorted, int E) {
    int e = blockIdx.x * blockDim.x + threadIdx.x;
    if (e < E) {
        int dst = ei[E + e];
        int pos = atomicAdd(&cursor[dst], 1);
        esorted[pos] = ei[e];
    }
}

// ---------------------------------------------------------------------------
// gather: agg[n] = x[n] + sum_{s in in-neighbors(n)} x[s]
// ---------------------------------------------------------------------------
__global__ void __launch_bounds__(256) gather_kernel(
    const float4* __restrict__ x, const int* __restrict__ rowstart,
    const int* __restrict__ esorted, float4* __restrict__ agg, int N)
{
    int warp = (blockIdx.x * blockDim.x + threadIdx.x) >> 5;
    int lane = threadIdx.x & 31;
    if (warp >= N) return;
    int node  = warp;
    int start = __ldg(&rowstart[node]);
    int end   = __ldg(&rowstart[node + 1]);

    float4 acc = x[node * 32 + lane];
    float4 a1 = make_float4(0.f, 0.f, 0.f, 0.f);
    float4 a2 = make_float4(0.f, 0.f, 0.f, 0.f);
    float4 a3 = make_float4(0.f, 0.f, 0.f, 0.f);

    int i = start;
    for (; i + 3 < end; i += 4) {
        int s0 = __ldg(&esorted[i]);
        int s1 = __ldg(&esorted[i + 1]);
        int s2 = __ldg(&esorted[i + 2]);
        int s3 = __ldg(&esorted[i + 3]);
        float4 v0 = x[s0 * 32 + lane];
        float4 v1 = x[s1 * 32 + lane];
        float4 v2 = x[s2 * 32 + lane];
        float4 v3 = x[s3 * 32 + lane];
        acc.x += v0.x; acc.y += v0.y; acc.z += v0.z; acc.w += v0.w;
        a1.x += v1.x; a1.y += v1.y; a1.z += v1.z; a1.w += v1.w;
        a2.x += v2.x; a2.y += v2.y; a2.z += v2.z; a2.w += v2.w;
        a3.x += v3.x; a3.y += v3.y; a3.z += v3.z; a3.w += v3.w;
    }
    for (; i < end; i++) {
        int s = __ldg(&esorted[i]);
        float4 v = x[s * 32 + lane];
        acc.x += v.x; acc.y += v.y; acc.z += v.z; acc.w += v.w;
    }
    acc.x += a1.x + a2.x + a3.x;
    acc.y += a1.y + a2.y + a3.y;
    acc.z += a1.z + a2.z + a3.z;
    acc.w += a1.w + a2.w + a3.w;
    agg[node * 32 + lane] = acc;
}

// ---------------------------------------------------------------------------
// Fused 2-GEMM MLP (3xTF32): C = relu(relu(A@W1+b1)@W2+b2), per 128-row tile.
// Intermediate T kept in smem (raw fp32, split to tf32 hi/lo at fragment load).
// ---------------------------------------------------------------------------
__device__ __forceinline__ uint32_t f2tf32(float f) {
    uint32_t r;
    asm("cvt.rna.tf32.f32 %0, %1;" : "=r"(r) : "f"(f));
    return r;
}
__device__ __forceinline__ void split2(float v, uint32_t& hi, uint32_t& lo) {
    hi = f2tf32(v);
    lo = f2tf32(v - __uint_as_float(hi));
}

__device__ __forceinline__ void mma_tf32(float d[4],
                                         const uint32_t a[4],
                                         const uint32_t b[2]) {
    asm volatile(
        "mma.sync.aligned.m16n8k8.row.col.f32.tf32.tf32.f32 "
        "{%0,%1,%2,%3}, {%4,%5,%6,%7}, {%8,%9}, {%0,%1,%2,%3};"
        : "+f"(d[0]), "+f"(d[1]), "+f"(d[2]), "+f"(d[3])
        : "r"(a[0]), "r"(a[1]), "r"(a[2]), "r"(a[3]),
          "r"(b[0]), "r"(b[1]));
}

#define AS_PITCH 36
#define WS_PITCH 136
#define T_PITCH  132
// region0: max(2*128*36, 128*132) = 16896 u32; region1: 2*32*136 = 8704 u32
#define R0_SIZE  16896
#define MLP_SMEM ((R0_SIZE + 2 * 32 * WS_PITCH) * 4)

__global__ void __launch_bounds__(256, 2) gin_mlp(
    const float* __restrict__ A,
    const float* __restrict__ W1, const float* __restrict__ b1,
    const float* __restrict__ W2, const float* __restrict__ b2,
    float* __restrict__ C, int N)
{
    extern __shared__ uint32_t sm[];
    uint32_t* AsHi = sm;                     // phase 1 (aliased with Traw)
    uint32_t* AsLo = sm + 128 * AS_PITCH;
    float*    Traw = (float*)sm;             // phases 2/3
    uint32_t* WsHi = sm + R0_SIZE;
    uint32_t* WsLo = WsHi + 32 * WS_PITCH;

    const int tid   = threadIdx.x;
    const int lane  = tid & 31;
    const int warp  = tid >> 5;
    const int warpM = warp >> 2;
    const int warpN = warp & 3;
    const int gid   = lane >> 2;
    const int tig   = lane & 3;
    const int row0  = blockIdx.x * 128;

    float acc[4][4][4];
    #pragma unroll
    for (int i = 0; i < 4; i++)
        #pragma unroll
        for (int j = 0; j < 4; j++)
            #pragma unroll
            for (int k = 0; k < 4; k++) acc[i][j][k] = 0.f;

    // ======================= Phase 1: T = A @ W1 =======================
    for (int kb = 0; kb < 4; kb++) {
        #pragma unroll
        for (int i = 0; i < 4; i++) {
            int idx = tid + i * 256;
            int r = idx >> 5;
            int c = idx & 31;
            float4 v = ((const float4*)W1)[(kb * 32 + r) * 32 + c];
            float* vp = (float*)&v;
            #pragma unroll
            for (int j = 0; j < 4; j++) {
                uint32_t hi, lo;
                split2(vp[j], hi, lo);
                WsHi[r * WS_PITCH + c * 4 + j] = hi;
                WsLo[r * WS_PITCH + c * 4 + j] = lo;
            }
        }
        #pragma unroll
        for (int i = 0; i < 4; i++) {
            int idx = tid + i * 256;
            int r  = idx >> 3;
            int c4 = idx & 7;
            int g = row0 + r;
            float4 v = make_float4(0.f, 0.f, 0.f, 0.f);
            if (g < N) v = ((const float4*)A)[g * 32 + kb * 8 + c4];
            float* vp = (float*)&v;
            uint4 hi4, lo4;
            uint32_t* hp = (uint32_t*)&hi4;
            uint32_t* lp = (uint32_t*)&lo4;
            #pragma unroll
            for (int j = 0; j < 4; j++) split2(vp[j], hp[j], lp[j]);
            *(uint4*)&AsHi[r * AS_PITCH + c4 * 4] = hi4;
            *(uint4*)&AsLo[r * AS_PITCH + c4 * 4] = lo4;
        }
        __syncthreads();

        #pragma unroll
        for (int ks = 0; ks < 4; ks++) {
            int k0 = ks * 8;
            uint32_t bH[4][2], bL[4][2];
            #pragma unroll
            for (int nt = 0; nt < 4; nt++) {
                int cb = warpN * 32 + nt * 8 + gid;
                bH[nt][0] = WsHi[(k0 + tig) * WS_PITCH + cb];
                bH[nt][1] = WsHi[(k0 + tig + 4) * WS_PITCH + cb];
                bL[nt][0] = WsLo[(k0 + tig) * WS_PITCH + cb];
                bL[nt][1] = WsLo[(k0 + tig + 4) * WS_PITCH + cb];
            }
            #pragma unroll
            for (int mt = 0; mt < 4; mt++) {
                int rb = warpM * 64 + mt * 16;
                uint32_t aH[4], aL[4];
                aH[0] = AsHi[(rb + gid) * AS_PITCH + k0 + tig];
                aH[1] = AsHi[(rb + gid + 8) * AS_PITCH + k0 + tig];
                aH[2] = AsHi[(rb + gid) * AS_PITCH + k0 + tig + 4];
                aH[3] = AsHi[(rb + gid + 8) * AS_PITCH + k0 + tig + 4];
                aL[0] = AsLo[(rb + gid) * AS_PITCH + k0 + tig];
                aL[1] = AsLo[(rb + gid + 8) * AS_PITCH + k0 + tig];
                aL[2] = AsLo[(rb + gid) * AS_PITCH + k0 + tig + 4];
                aL[3] = AsLo[(rb + gid + 8) * AS_PITCH + k0 + tig + 4];
                #pragma unroll
                for (int nt = 0; nt < 4; nt++) {
                    mma_tf32(acc[mt][nt], aH, bH[nt]);
                    mma_tf32(acc[mt][nt], aL, bH[nt]);
                    mma_tf32(acc[mt][nt], aH, bL[nt]);
                }
            }
        }
        __syncthreads();
    }

    // ========== Phase 2: T = relu(T + b1) -> smem (raw fp32) ==========
    #pragma unroll
    for (int nt = 0; nt < 4; nt++) {
        int cb = warpN * 32 + nt * 8 + tig * 2;
        float2 bv = *(const float2*)&b1[cb];
        #pragma unroll
        for (int mt = 0; mt < 4; mt++) {
            int r0 = warpM * 64 + mt * 16 + gid;
            float2 o0, o1;
            o0.x = fmaxf(acc[mt][nt][0] + bv.x, 0.f);
            o0.y = fmaxf(acc[mt][nt][1] + bv.y, 0.f);
            o1.x = fmaxf(acc[mt][nt][2] + bv.x, 0.f);
            o1.y = fmaxf(acc[mt][nt][3] + bv.y, 0.f);
            *(float2*)&Traw[r0 * T_PITCH + cb]       = o0;
            *(float2*)&Traw[(r0 + 8) * T_PITCH + cb] = o1;
        }
    }
    __syncthreads();

    // ======================= Phase 3: C = T @ W2 =======================
    #pragma unroll
    for (int i = 0; i < 4; i++)
        #pragma unroll
        for (int j = 0; j < 4; j++)
            #pragma unroll
            for (int k = 0; k < 4; k++) acc[i][j][k] = 0.f;

    for (int kb = 0; kb < 4; kb++) {
        #pragma unroll
        for (int i = 0; i < 4; i++) {
            int idx = tid + i * 256;
            int r = idx >> 5;
            int c = idx & 31;
            float4 v = ((const float4*)W2)[(kb * 32 + r) * 32 + c];
            float* vp = (float*)&v;
            #pragma unroll
            for (int j = 0; j < 4; j++) {
                uint32_t hi, lo;
                split2(vp[j], hi, lo);
                WsHi[r * WS_PITCH + c * 4 + j] = hi;
                WsLo[r * WS_PITCH + c * 4 + j] = lo;
            }
        }
        __syncthreads();

        #pragma unroll
        for (int ks = 0; ks < 4; ks++) {
            int k0  = ks * 8;            // within chunk
            int kg  = kb * 32 + k0;      // global k into T
            uint32_t bH[4][2], bL[4][2];
            #pragma unroll
            for (int nt = 0; nt < 4; nt++) {
                int cb = warpN * 32 + nt * 8 + gid;
                bH[nt][0] = WsHi[(k0 + tig) * WS_PITCH + cb];
                bH[nt][1] = WsHi[(k0 + tig + 4) * WS_PITCH + cb];
                bL[nt][0] = WsLo[(k0 + tig) * WS_PITCH + cb];
                bL[nt][1] = WsLo[(k0 + tig + 4) * WS_PITCH + cb];
            }
            #pragma unroll
            for (int mt = 0; mt < 4; mt++) {
                int rb = warpM * 64 + mt * 16;
                float ar[4];
                ar[0] = Traw[(rb + gid) * T_PITCH + kg + tig];
                ar[1] = Traw[(rb + gid + 8) * T_PITCH + kg + tig];
                ar[2] = Traw[(rb + gid) * T_PITCH + kg + tig + 4];
                ar[3] = Traw[(rb + gid + 8) * T_PITCH + kg + tig + 4];
                uint32_t aH[4], aL[4];
                #pragma unroll
                for (int q = 0; q < 4; q++) split2(ar[q], aH[q], aL[q]);
                #pragma unroll
                for (int nt = 0; nt < 4; nt++) {
                    mma_tf32(acc[mt][nt], aH, bH[nt]);
                    mma_tf32(acc[mt][nt], aL, bH[nt]);
                    mma_tf32(acc[mt][nt], aH, bL[nt]);
                }
            }
        }
        __syncthreads();
    }

    // ================= Epilogue: relu(acc + b2) -> gmem =================
    #pragma unroll
    for (int nt = 0; nt < 4; nt++) {
        int cb = warpN * 32 + nt * 8;
        float2 bv = *(const float2*)&b2[cb + tig * 2];
        #pragma unroll
        for (int mt = 0; mt < 4; mt++) {
            int r0 = row0 + warpM * 64 + mt * 16 + gid;
            int r1 = r0 + 8;
            if (r0 < N) {
                float2 o;
                o.x = fmaxf(acc[mt][nt][0] + bv.x, 0.f);
                o.y = fmaxf(acc[mt][nt][1] + bv.y, 0.f);
                *(float2*)&C[(long long)r0 * DIM + cb + tig * 2] = o;
            }
            if (r1 < N) {
                float2 o;
                o.x = fmaxf(acc[mt][nt][2] + bv.x, 0.f);
                o.y = fmaxf(acc[mt][nt][3] + bv.y, 0.f);
                *(float2*)&C[(long long)r1 * DIM + cb + tig * 2] = o;
            }
        }
    }
}

// ---------------------------------------------------------------------------
// pool_ffn
// ---------------------------------------------------------------------------
__global__ void __launch_bounds__(256) pool_ffn(
    const float* __restrict__ h, const int* __restrict__ batch, int N,
    const float* __restrict__ wf1, const float* __restrict__ bf1,
    const float* __restrict__ wf2, const float* __restrict__ bf2,
    float* __restrict__ out)
{
    const int g    = blockIdx.x;
    const int tid  = threadIdx.x;
    const int f    = tid & 127;
    const int half = tid >> 7;

    int start, end;
    {
        int v = g;
        int lo = 0, hi = N;
        while (lo < hi) { int m = (lo + hi) >> 1; if (batch[m] < v) lo = m + 1; else hi = m; }
        start = lo;
        v = g + 1; lo = start; hi = N;
        while (lo < hi) { int m = (lo + hi) >> 1; if (batch[m] < v) lo = m + 1; else hi = m; }
        end = lo;
    }

    float a0 = 0.f, a1 = 0.f, a2 = 0.f, a3 = 0.f;
    int n = start + half;
    for (; n + 6 < end; n += 8) {
        a0 += h[(long long)(n    ) * DIM + f];
        a1 += h[(long long)(n + 2) * DIM + f];
        a2 += h[(long long)(n + 4) * DIM + f];
        a3 += h[(long long)(n + 6) * DIM + f];
    }
    for (; n < end; n += 2) a0 += h[(long long)n * DIM + f];
    float s = (a0 + a1) + (a2 + a3);

    __shared__ float ps[2][128];
    __shared__ float pooled_s[128];
    __shared__ float h1[128];
    __shared__ float o[10];

    ps[half][f] = s;
    __syncthreads();

    float cnt = fmaxf((float)(end - start), 1.0f);
    if (tid < 128) pooled_s[tid] = (ps[0][tid] + ps[1][tid]) / cnt;
    __syncthreads();

    if (tid < 128) {
        float acc = bf1[tid];
        #pragma unroll 8
        for (int k = 0; k < 128; k++) acc = fmaf(pooled_s[k], wf1[k * 128 + tid], acc);
        h1[tid] = fmaxf(acc, 0.f);
    }
    __syncthreads();

    if (tid < 10) {
        float acc = bf2[tid];
        #pragma unroll 8
        for (int k = 0; k < 128; k++) acc = fmaf(h1[k], wf2[k * 10 + tid], acc);
        o[tid] = acc;
    }
    __syncthreads();

    if (tid == 0) {
        float m = o[0];
        #pragma unroll
        for (int c = 1; c < 10; c++) m = fmaxf(m, o[c]);
        float e[10]; float sum = 0.f;
        #pragma unroll
        for (int c = 0; c < 10; c++) { e[c] = __expf(o[c] - m); sum += e[c]; }
        float inv = 1.f / sum;
        #pragma unroll
        for (int c = 0; c < 10; c++) out[g * 10 + c] = e[c] * inv;
    }
}

// ---------------------------------------------------------------------------
extern "C" void kernel_launch(void* const* d_in, const int* in_sizes, int n_in,
                              void* d_out, int out_size) {
    const float* x     = (const float*)d_in[0];
    const int*   ei    = (const int*)d_in[1];
    const int*   batch = (const int*)d_in[2];
    const float* w[6] = { (const float*)d_in[3],  (const float*)d_in[5],
                          (const float*)d_in[7],  (const float*)d_in[9],
                          (const float*)d_in[11], (const float*)d_in[13] };
    const float* b[6] = { (const float*)d_in[4],  (const float*)d_in[6],
                          (const float*)d_in[8],  (const float*)d_in[10],
                          (const float*)d_in[12], (const float*)d_in[14] };
    const float* wf1 = (const float*)d_in[15];
    const float* bf1 = (const float*)d_in[16];
    const float* wf2 = (const float*)d_in[17];
    const float* bf2 = (const float*)d_in[18];

    const int N = in_sizes[0] / DIM;
    const int E = in_sizes[1] / 2;

    float *agg, *hbuf;
    int *counts, *rowstart, *cursor, *esorted;
    cudaGetSymbolAddress((void**)&agg,      g_agg);
    cudaGetSymbolAddress((void**)&hbuf,     g_h);
    cudaGetSymbolAddress((void**)&counts,   g_counts);
    cudaGetSymbolAddress((void**)&rowstart, g_rowstart);
    cudaGetSymbolAddress((void**)&cursor,   g_cursor);
    cudaGetSymbolAddress((void**)&esorted,  g_esorted);

    static bool attr_set = false;
    if (!attr_set) {
        cudaFuncSetAttribute(gin_mlp,
                             cudaFuncAttributeMaxDynamicSharedMemorySize,
                             MLP_SMEM);
        attr_set = true;
    }

    // ---- CSR build ----
    cudaMemsetAsync(counts, 0, N * sizeof(int));
    const int eb = (E + 255) / 256;
    hist_kernel<<<eb, 256>>>(ei, counts, E);
    scan_kernel<<<1, 1024>>>(counts, rowstart, cursor, N);
    fill_kernel<<<eb, 256>>>(ei, cursor, esorted, E);

    const int gather_blocks = (N * 32 + 255) / 256;
    const int gemm_blocks = (N + 127) / 128;

    for (int L = 0; L < 3; L++) {
        const float* in = (L == 0) ? x : hbuf;
        gather_kernel<<<gather_blocks, 256>>>((const float4*)in, rowstart, esorted,
                                              (float4*)agg, N);
        gin_mlp<<<gemm_blocks, 256, MLP_SMEM>>>(agg, w[2 * L], b[2 * L],
                                                w[2 * L + 1], b[2 * L + 1], hbuf, N);
    }
    pool_ffn<<<NGRAPH, 256>>>(hbuf, batch, N, wf1, bf1, wf2, bf2, (float*)d_out);
}

// round 7
// speedup vs baseline: 2.4148x; 1.0001x over previous
#include <cuda_runtime.h>
#include <cuda_bf16.h>
#include <math.h>
#include <stdint.h>

#define MAXN 50000
#define MAXE 600000
#define DIM  128
#define NGRAPH 64

// Scratch buffers (no cudaMalloc allowed)
__device__ __align__(16) float g_agg[MAXN * DIM];
__device__ __align__(16) float g_h  [MAXN * DIM];
__device__ int g_counts  [MAXN];
__device__ int g_rowstart[MAXN + 1];
__device__ int g_cursor  [MAXN];
__device__ int g_esorted [MAXE];
// Pre-converted tf32 hi/lo for the 6 layer weight matrices (each 128x128)
__device__ __align__(16) uint32_t g_whi[6 * 16384];
__device__ __align__(16) uint32_t g_wlo[6 * 16384];

// ---------------------------------------------------------------------------
// tf32 helpers
// ---------------------------------------------------------------------------
__device__ __forceinline__ uint32_t f2tf32(float f) {
    uint32_t r;
    asm("cvt.rna.tf32.f32 %0, %1;" : "=r"(r) : "f"(f));
    return r;
}
__device__ __forceinline__ void split2(float v, uint32_t& hi, uint32_t& lo) {
    hi = f2tf32(v);
    lo = f2tf32(v - __uint_as_float(hi));
}
__device__ __forceinline__ void mma_tf32(float d[4],
                                         const uint32_t a[4],
                                         const uint32_t b[2]) {
    asm volatile(
        "mma.sync.aligned.m16n8k8.row.col.f32.tf32.tf32.f32 "
        "{%0,%1,%2,%3}, {%4,%5,%6,%7}, {%8,%9}, {%0,%1,%2,%3};"
        : "+f"(d[0]), "+f"(d[1]), "+f"(d[2]), "+f"(d[3])
        : "r"(a[0]), "r"(a[1]), "r"(a[2]), "r"(a[3]),
          "r"(b[0]), "r"(b[1]));
}

// cp.async helpers
__device__ __forceinline__ uint32_t smem_u32(const void* p) {
    return (uint32_t)__cvta_generic_to_shared(p);
}
__device__ __forceinline__ void cpa16(uint32_t dst, const void* src, int srcsize) {
    asm volatile("cp.async.cg.shared.global [%0], [%1], 16, %2;"
                 :: "r"(dst), "l"(src), "r"(srcsize));
}
#define CP_COMMIT() asm volatile("cp.async.commit_group;")
#define CP_WAIT1()  asm volatile("cp.async.wait_group 1;")
#define CP_WAIT0()  asm volatile("cp.async.wait_group 0;")

// ---------------------------------------------------------------------------
// convert_w: split all 6 weight matrices into tf32 hi/lo (one-time per launch)
// ---------------------------------------------------------------------------
__global__ void convert_w(const float* __restrict__ w0, const float* __restrict__ w1,
                          const float* __restrict__ w2, const float* __restrict__ w3,
                          const float* __restrict__ w4, const float* __restrict__ w5,
                          uint32_t* __restrict__ hi, uint32_t* __restrict__ lo) {
    int i = blockIdx.x * 256 + threadIdx.x;      // 0 .. 6*16384-1
    int m = i >> 14;
    int off = i & 16383;
    const float* w = (m == 0) ? w0 : (m == 1) ? w1 : (m == 2) ? w2
                   : (m == 3) ? w3 : (m == 4) ? w4 : w5;
    float v = w[off];
    uint32_t h = f2tf32(v);
    hi[i] = h;
    lo[i] = f2tf32(v - __uint_as_float(h));
}

// ---------------------------------------------------------------------------
// CSR build
// ---------------------------------------------------------------------------
__global__ void hist_kernel(const int* __restrict__ ei, int* __restrict__ counts, int E) {
    int e = blockIdx.x * blockDim.x + threadIdx.x;
    if (e < E) atomicAdd(&counts[ei[E + e]], 1);
}

__global__ void __launch_bounds__(1024) scan_kernel(
    const int* __restrict__ counts, int* __restrict__ rowstart,
    int* __restrict__ cursor, int N)
{
    __shared__ int sums[1024];
    const int tid = threadIdx.x;
    const int chunk = (N + 1023) / 1024;
    const int lo = tid * chunk;
    const int hi = min(lo + chunk, N);

    int s = 0;
    for (int i = lo; i < hi; i++) s += counts[i];
    sums[tid] = s;
    __syncthreads();

    for (int d = 1; d < 1024; d <<= 1) {
        int v = (tid >= d) ? sums[tid - d] : 0;
        __syncthreads();
        sums[tid] += v;
        __syncthreads();
    }
    int run = (tid == 0) ? 0 : sums[tid - 1];
    for (int i = lo; i < hi; i++) {
        rowstart[i] = run;
        cursor[i]   = run;
        run += counts[i];
    }
    if (tid == 1023 && N > 0) rowstart[N] = run;
}

__global__ void fill_kernel(const int* __restrict__ ei, int* __restrict__ cursor,
                            int* __restrict__ esorted, int E) {
    int e = blockIdx.x * blockDim.x + threadIdx.x;
    if (e < E) {
        int dst = ei[E + e];
        int pos = atomicAdd(&cursor[dst], 1);
        esorted[pos] = ei[e];
    }
}

// ---------------------------------------------------------------------------
// gather: agg[n] = x[n] + sum_{s in in-neighbors(n)} x[s]
// ---------------------------------------------------------------------------
__global__ void __launch_bounds__(256) gather_kernel(
    const float4* __restrict__ x, const int* __restrict__ rowstart,
    const int* __restrict__ esorted, float4* __restrict__ agg, int N)
{
    int warp = (blockIdx.x * blockDim.x + threadIdx.x) >> 5;
    int lane = threadIdx.x & 31;
    if (warp >= N) return;
    int node  = warp;
    int start = __ldg(&rowstart[node]);
    int end   = __ldg(&rowstart[node + 1]);

    float4 acc = x[node * 32 + lane];
    float4 a1 = make_float4(0.f, 0.f, 0.f, 0.f);
    float4 a2 = make_float4(0.f, 0.f, 0.f, 0.f);
    float4 a3 = make_float4(0.f, 0.f, 0.f, 0.f);

    int i = start;
    for (; i + 3 < end; i += 4) {
        int s0 = __ldg(&esorted[i]);
        int s1 = __ldg(&esorted[i + 1]);
        int s2 = __ldg(&esorted[i + 2]);
        int s3 = __ldg(&esorted[i + 3]);
        float4 v0 = x[s0 * 32 + lane];
        float4 v1 = x[s1 * 32 + lane];
        float4 v2 = x[s2 * 32 + lane];
        float4 v3 = x[s3 * 32 + lane];
        acc.x += v0.x; acc.y += v0.y; acc.z += v0.z; acc.w += v0.w;
        a1.x += v1.x; a1.y += v1.y; a1.z += v1.z; a1.w += v1.w;
        a2.x += v2.x; a2.y += v2.y; a2.z += v2.z; a2.w += v2.w;
        a3.x += v3.x; a3.y += v3.y; a3.z += v3.z; a3.w += v3.w;
    }
    for (; i < end; i++) {
        int s = __ldg(&esorted[i]);
        float4 v = x[s * 32 + lane];
        acc.x += v.x; acc.y += v.y; acc.z += v.z; acc.w += v.w;
    }
    acc.x += a1.x + a2.x + a3.x;
    acc.y += a1.y + a2.y + a3.y;
    acc.z += a1.z + a2.z + a3.z;
    acc.w += a1.w + a2.w + a3.w;
    agg[node * 32 + lane] = acc;
}

// ---------------------------------------------------------------------------
// Fused, pipelined 2-GEMM MLP (3xTF32):
//   C = relu(relu(A@W1+b1)@W2+b2), 128-row tile per block.
//   K split into 8 chunks of 16; cp.async double-buffered loads overlap mma.
//   A (and smem-resident T) stored raw fp32, split to tf32 hi/lo at frag load.
// ---------------------------------------------------------------------------
#define AP 20        // A buffer pitch (f32)
#define WP 136       // W buffer pitch (u32)
#define TP 132       // T pitch (f32)
#define R0 16896     // region0 size in u32: max(T = 128*132, A db = 2*2560)
#define WBUF 4352    // per W buffer: hi 16*136 + lo 16*136
#define ABUF 2560    // per A buffer: 128*20 f32
#define MLP_SMEM ((R0 + 2 * WBUF) * 4)

// Copy A chunk kc (128 rows x 16 k, raw fp32) into Ab via cp.async
__device__ __forceinline__ void load_A_chunk(const float* A, int row0, int N,
                                             int kc, float* Ab, int tid) {
    #pragma unroll
    for (int i = 0; i < 2; i++) {
        int idx = tid + i * 256;          // 0..511
        int r  = idx >> 2;                // 0..127
        int c4 = idx & 3;                 // 0..3 (float4 within chunk)
        int g = row0 + r;
        const float4* src = ((const float4*)A) + ((long long)g * 32 + kc * 4 + c4);
        cpa16(smem_u32(&Ab[r * AP + c4 * 4]), src, (g < N) ? 16 : 0);
    }
}

// Copy W chunk kc (16 k-rows x 128 cols, hi+lo) into Wbuf via cp.async
__device__ __forceinline__ void load_W_chunk(const uint32_t* whi, const uint32_t* wlo,
                                             int kc, uint32_t* Wbuf, int tid) {
    #pragma unroll
    for (int i = 0; i < 2; i++) {
        int idx = tid + i * 256;          // 0..511
        int r = idx >> 5;                 // 0..15
        int c = idx & 31;                 // 16B group
        cpa16(smem_u32(&Wbuf[r * WP + c * 4]),        whi + (kc * 16 + r) * 128 + c * 4, 16);
        cpa16(smem_u32(&Wbuf[WBUF / 2 + r * WP + c * 4]), wlo + (kc * 16 + r) * 128 + c * 4, 16);
    }
}

// Compute one K=16 chunk: raw A (pitch P) split at load, W already tf32 hi/lo
template<int P>
__device__ __forceinline__ void compute_chunk(
    const float* Ab, const uint32_t* WbH, const uint32_t* WbL,
    float acc[4][4][4], int warpM, int warpN, int gid, int tig)
{
    #pragma unroll
    for (int ks = 0; ks < 2; ks++) {
        int k0 = ks * 8;
        uint32_t bH[4][2], bL[4][2];
        #pragma unroll
        for (int nt = 0; nt < 4; nt++) {
            int cb = warpN * 32 + nt * 8 + gid;
            bH[nt][0] = WbH[(k0 + tig) * WP + cb];
            bH[nt][1] = WbH[(k0 + tig + 4) * WP + cb];
            bL[nt][0] = WbL[(k0 + tig) * WP + cb];
            bL[nt][1] = WbL[(k0 + tig + 4) * WP + cb];
        }
        #pragma unroll
        for (int mt = 0; mt < 4; mt++) {
            int rb = warpM * 64 + mt * 16;
            float ar[4];
            ar[0] = Ab[(rb + gid) * P + k0 + tig];
            ar[1] = Ab[(rb + gid + 8) * P + k0 + tig];
            ar[2] = Ab[(rb + gid) * P + k0 + tig + 4];
            ar[3] = Ab[(rb + gid + 8) * P + k0 + tig + 4];
            uint32_t aH[4], aL[4];
            #pragma unroll
            for (int q = 0; q < 4; q++) split2(ar[q], aH[q], aL[q]);
            #pragma unroll
            for (int nt = 0; nt < 4; nt++) {
                mma_tf32(acc[mt][nt], aH, bH[nt]);
                mma_tf32(acc[mt][nt], aL, bH[nt]);
                mma_tf32(acc[mt][nt], aH, bL[nt]);
            }
        }
    }
}

__global__ void __launch_bounds__(256, 2) gin_mlp(
    const float* __restrict__ A,
    const uint32_t* __restrict__ w1hi, const uint32_t* __restrict__ w1lo,
    const float* __restrict__ b1,
    const uint32_t* __restrict__ w2hi, const uint32_t* __restrict__ w2lo,
    const float* __restrict__ b2,
    float* __restrict__ C, int N)
{
    extern __shared__ uint32_t sm[];
    float*    Araw = (float*)sm;            // phase 1: [2][ABUF]
    float*    Traw = (float*)sm;            // phases 2/3: [128][TP]
    uint32_t* Wb   = sm + R0;               // [2][WBUF]  (hi at +0, lo at +WBUF/2)

    const int tid   = threadIdx.x;
    const int lane  = tid & 31;
    const int warp  = tid >> 5;
    const int warpM = warp >> 2;
    const int warpN = warp & 3;
    const int gid   = lane >> 2;
    const int tig   = lane & 3;
    const int row0  = blockIdx.x * 128;

    float acc[4][4][4];
    #pragma unroll
    for (int i = 0; i < 4; i++)
        #pragma unroll
        for (int j = 0; j < 4; j++)
            #pragma unroll
            for (int k = 0; k < 4; k++) acc[i][j][k] = 0.f;

    // ================= Phase 1: T = A @ W1 (pipelined) =================
    load_A_chunk(A, row0, N, 0, Araw, tid);
    load_W_chunk(w1hi, w1lo, 0, Wb, tid);
    CP_COMMIT();

    for (int c = 0; c < 8; c++) {
        int cur = c & 1;
        if (c < 7) {
            int nxt = (c + 1) & 1;
            load_A_chunk(A, row0, N, c + 1, Araw + nxt * ABUF, tid);
            load_W_chunk(w1hi, w1lo, c + 1, Wb + nxt * WBUF, tid);
            CP_COMMIT();
            CP_WAIT1();
        } else {
            CP_WAIT0();
        }
        __syncthreads();
        compute_chunk<AP>(Araw + cur * ABUF,
                          Wb + cur * WBUF, Wb + cur * WBUF + WBUF / 2,
                          acc, warpM, warpN, gid, tig);
        __syncthreads();
    }

    // ========== Phase 2: T = relu(T + b1) -> smem (raw fp32) ==========
    // region1 is free now: prefetch W2 chunk 0 while we write T.
    load_W_chunk(w2hi, w2lo, 0, Wb, tid);
    CP_COMMIT();

    #pragma unroll
    for (int nt = 0; nt < 4; nt++) {
        int cb = warpN * 32 + nt * 8 + tig * 2;
        float2 bv = *(const float2*)&b1[cb];
        #pragma unroll
        for (int mt = 0; mt < 4; mt++) {
            int r0 = warpM * 64 + mt * 16 + gid;
            float2 o0, o1;
            o0.x = fmaxf(acc[mt][nt][0] + bv.x, 0.f);
            o0.y = fmaxf(acc[mt][nt][1] + bv.y, 0.f);
            o1.x = fmaxf(acc[mt][nt][2] + bv.x, 0.f);
            o1.y = fmaxf(acc[mt][nt][3] + bv.y, 0.f);
            *(float2*)&Traw[r0 * TP + cb]       = o0;
            *(float2*)&Traw[(r0 + 8) * TP + cb] = o1;
        }
    }
    #pragma unroll
    for (int i = 0; i < 4; i++)
        #pragma unroll
        for (int j = 0; j < 4; j++)
            #pragma unroll
            for (int k = 0; k < 4; k++) acc[i][j][k] = 0.f;
    __syncthreads();

    // ================= Phase 3: C = T @ W2 (pipelined) =================
    for (int c = 0; c < 8; c++) {
        int cur = c & 1;
        if (c < 7) {
            int nxt = (c + 1) & 1;
            load_W_chunk(w2hi, w2lo, c + 1, Wb + nxt * WBUF, tid);
            CP_COMMIT();
            CP_WAIT1();
        } else {
            CP_WAIT0();
        }
        __syncthreads();
        compute_chunk<TP>(Traw + c * 16,
                          Wb + cur * WBUF, Wb + cur * WBUF + WBUF / 2,
                          acc, warpM, warpN, gid, tig);
        __syncthreads();
    }

    // ================= Epilogue: relu(acc + b2) -> gmem =================
    #pragma unroll
    for (int nt = 0; nt < 4; nt++) {
        int cb = warpN * 32 + nt * 8;
        float2 bv = *(const float2*)&b2[cb + tig * 2];
        #pragma unroll
        for (int mt = 0; mt < 4; mt++) {
            int r0 = row0 + warpM * 64 + mt * 16 + gid;
            int r1 = r0 + 8;
            if (r0 < N) {
                float2 o;
                o.x = fmaxf(acc[mt][nt][0] + bv.x, 0.f);
                o.y = fmaxf(acc[mt][nt][1] + bv.y, 0.f);
                *(float2*)&C[(long long)r0 * DIM + cb + tig * 2] = o;
            }
            if (r1 < N) {
                float2 o;
                o.x = fmaxf(acc[mt][nt][2] + bv.x, 0.f);
                o.y = fmaxf(acc[mt][nt][3] + bv.y, 0.f);
                *(float2*)&C[(long long)r1 * DIM + cb + tig * 2] = o;
            }
        }
    }
}

// ---------------------------------------------------------------------------
// pool_ffn
// ---------------------------------------------------------------------------
__global__ void __launch_bounds__(256) pool_ffn(
    const float* __restrict__ h, const int* __restrict__ batch, int N,
    const float* __restrict__ wf1, const float* __restrict__ bf1,
    const float* __restrict__ wf2, const float* __restrict__ bf2,
    float* __restrict__ out)
{
    const int g    = blockIdx.x;
    const int tid  = threadIdx.x;
    const int f    = tid & 127;
    const int half = tid >> 7;

    int start, end;
    {
        int v = g;
        int lo = 0, hi = N;
        while (lo < hi) { int m = (lo + hi) >> 1; if (batch[m] < v) lo = m + 1; else hi = m; }
        start = lo;
        v = g + 1; lo = start; hi = N;
        while (lo < hi) { int m = (lo + hi) >> 1; if (batch[m] < v) lo = m + 1; else hi = m; }
        end = lo;
    }

    float a0 = 0.f, a1 = 0.f, a2 = 0.f, a3 = 0.f;
    int n = start + half;
    for (; n + 6 < end; n += 8) {
        a0 += h[(long long)(n    ) * DIM + f];
        a1 += h[(long long)(n + 2) * DIM + f];
        a2 += h[(long long)(n + 4) * DIM + f];
        a3 += h[(long long)(n + 6) * DIM + f];
    }
    for (; n < end; n += 2) a0 += h[(long long)n * DIM + f];
    float s = (a0 + a1) + (a2 + a3);

    __shared__ float ps[2][128];
    __shared__ float pooled_s[128];
    __shared__ float h1[128];
    __shared__ float o[10];

    ps[half][f] = s;
    __syncthreads();

    float cnt = fmaxf((float)(end - start), 1.0f);
    if (tid < 128) pooled_s[tid] = (ps[0][tid] + ps[1][tid]) / cnt;
    __syncthreads();

    if (tid < 128) {
        float acc = bf1[tid];
        #pragma unroll 8
        for (int k = 0; k < 128; k++) acc = fmaf(pooled_s[k], wf1[k * 128 + tid], acc);
        h1[tid] = fmaxf(acc, 0.f);
    }
    __syncthreads();

    if (tid < 10) {
        float acc = bf2[tid];
        #pragma unroll 8
        for (int k = 0; k < 128; k++) acc = fmaf(h1[k], wf2[k * 10 + tid], acc);
        o[tid] = acc;
    }
    __syncthreads();

    if (tid == 0) {
        float m = o[0];
        #pragma unroll
        for (int c = 1; c < 10; c++) m = fmaxf(m, o[c]);
        float e[10]; float sum = 0.f;
        #pragma unroll
        for (int c = 0; c < 10; c++) { e[c] = __expf(o[c] - m); sum += e[c]; }
        float inv = 1.f / sum;
        #pragma unroll
        for (int c = 0; c < 10; c++) out[g * 10 + c] = e[c] * inv;
    }
}

// ---------------------------------------------------------------------------
extern "C" void kernel_launch(void* const* d_in, const int* in_sizes, int n_in,
                              void* d_out, int out_size) {
    const float* x     = (const float*)d_in[0];
    const int*   ei    = (const int*)d_in[1];
    const int*   batch = (const int*)d_in[2];
    const float* w[6] = { (const float*)d_in[3],  (const float*)d_in[5],
                          (const float*)d_in[7],  (const float*)d_in[9],
                          (const float*)d_in[11], (const float*)d_in[13] };
    const float* b[6] = { (const float*)d_in[4],  (const float*)d_in[6],
                          (const float*)d_in[8],  (const float*)d_in[10],
                          (const float*)d_in[12], (const float*)d_in[14] };
    const float* wf1 = (const float*)d_in[15];
    const float* bf1 = (const float*)d_in[16];
    const float* wf2 = (const float*)d_in[17];
    const float* bf2 = (const float*)d_in[18];

    const int N = in_sizes[0] / DIM;
    const int E = in_sizes[1] / 2;

    float *agg, *hbuf;
    int *counts, *rowstart, *cursor, *esorted;
    uint32_t *whi, *wlo;
    cudaGetSymbolAddress((void**)&agg,      g_agg);
    cudaGetSymbolAddress((void**)&hbuf,     g_h);
    cudaGetSymbolAddress((void**)&counts,   g_counts);
    cudaGetSymbolAddress((void**)&rowstart, g_rowstart);
    cudaGetSymbolAddress((void**)&cursor,   g_cursor);
    cudaGetSymbolAddress((void**)&esorted,  g_esorted);
    cudaGetSymbolAddress((void**)&whi,      g_whi);
    cudaGetSymbolAddress((void**)&wlo,      g_wlo);

    static bool attr_set = false;
    if (!attr_set) {
        cudaFuncSetAttribute(gin_mlp,
                             cudaFuncAttributeMaxDynamicSharedMemorySize,
                             MLP_SMEM);
        attr_set = true;
    }

    // ---- one-time prep: weight conversion + CSR build ----
    convert_w<<<384, 256>>>(w[0], w[1], w[2], w[3], w[4], w[5], whi, wlo);
    cudaMemsetAsync(counts, 0, N * sizeof(int));
    const int eb = (E + 255) / 256;
    hist_kernel<<<eb, 256>>>(ei, counts, E);
    scan_kernel<<<1, 1024>>>(counts, rowstart, cursor, N);
    fill_kernel<<<eb, 256>>>(ei, cursor, esorted, E);

    const int gather_blocks = (N * 32 + 255) / 256;
    const int gemm_blocks = (N + 127) / 128;

    for (int L = 0; L < 3; L++) {
        const float* in = (L == 0) ? x : hbuf;
        gather_kernel<<<gather_blocks, 256>>>((const float4*)in, rowstart, esorted,
                                              (float4*)agg, N);
        gin_mlp<<<gemm_blocks, 256, MLP_SMEM>>>(
            agg,
            whi + (2 * L) * 16384,     wlo + (2 * L) * 16384,     b[2 * L],
            whi + (2 * L + 1) * 16384, wlo + (2 * L + 1) * 16384, b[2 * L + 1],
            hbuf, N);
    }
    pool_ffn<<<NGRAPH, 256>>>(hbuf, batch, N, wf1, bf1, wf2, bf2, (float*)d_out);
}